// round 1
// baseline (speedup 1.0000x reference)
#include <cuda_runtime.h>

// QAttentionLayer: out[..., i] = cumprod_{j<=i}( cos(x_j) * cos(w_j) )
// x: [16384, 256, 10] fp32, weights: [10] fp32, out: same shape as x.
//
// Streaming kernel: each thread owns 2 consecutive rows (20 floats = 5 float4
// loads / 5 float4 stores). Warp-contiguous 2560B spans keep DRAM traffic at
// exactly the footprint (L1 absorbs per-instruction sector over-fetch).

#define NQ 10

__global__ __launch_bounds__(256)
void qattn_cumprod_kernel(const float* __restrict__ x,
                          const float* __restrict__ w,
                          float* __restrict__ out,
                          long long n_threads)
{
    long long t = (long long)blockIdx.x * blockDim.x + threadIdx.x;
    if (t >= n_threads) return;

    // cos(weights): 10 broadcast loads, L1-resident after first warp.
    float cw[NQ];
#pragma unroll
    for (int i = 0; i < NQ; i++) cw[i] = __cosf(__ldg(&w[i]));

    const float4* __restrict__ xv = reinterpret_cast<const float4*>(x);
    float4*       __restrict__ ov = reinterpret_cast<float4*>(out);

    long long base = t * 5;  // 5 float4 = 20 floats = 2 rows of NQ

    // Front-batch all loads (MLP=5) before any dependent math.
    float4 a0 = xv[base + 0];
    float4 a1 = xv[base + 1];
    float4 a2 = xv[base + 2];
    float4 a3 = xv[base + 3];
    float4 a4 = xv[base + 4];

    float v[20];
    v[0]=a0.x; v[1]=a0.y; v[2]=a0.z;  v[3]=a0.w;
    v[4]=a1.x; v[5]=a1.y; v[6]=a1.z;  v[7]=a1.w;
    v[8]=a2.x; v[9]=a2.y; v[10]=a2.z; v[11]=a2.w;
    v[12]=a3.x; v[13]=a3.y; v[14]=a3.z; v[15]=a3.w;
    v[16]=a4.x; v[17]=a4.y; v[18]=a4.z; v[19]=a4.w;

    // Row 0: cumulative product of cos(x_i)*cos(w_i)
    float run = 1.0f;
#pragma unroll
    for (int i = 0; i < NQ; i++) {
        run *= __cosf(v[i]) * cw[i];
        v[i] = run;
    }
    // Row 1
    run = 1.0f;
#pragma unroll
    for (int i = 0; i < NQ; i++) {
        run *= __cosf(v[NQ + i]) * cw[i];
        v[NQ + i] = run;
    }

    a0.x=v[0];  a0.y=v[1];  a0.z=v[2];  a0.w=v[3];
    a1.x=v[4];  a1.y=v[5];  a1.z=v[6];  a1.w=v[7];
    a2.x=v[8];  a2.y=v[9];  a2.z=v[10]; a2.w=v[11];
    a3.x=v[12]; a3.y=v[13]; a3.z=v[14]; a3.w=v[15];
    a4.x=v[16]; a4.y=v[17]; a4.z=v[18]; a4.w=v[19];

    ov[base + 0] = a0;
    ov[base + 1] = a1;
    ov[base + 2] = a2;
    ov[base + 3] = a3;
    ov[base + 4] = a4;
}

extern "C" void kernel_launch(void* const* d_in, const int* in_sizes, int n_in,
                              void* d_out, int out_size)
{
    const float* x = (const float*)d_in[0];   // [16384*256*10] fp32
    const float* w = (const float*)d_in[1];   // [10] fp32
    float* out = (float*)d_out;

    long long total = (long long)in_sizes[0];        // 41,943,040
    long long n_threads = total / 20;                // 2 rows (20 floats) per thread
    int block = 256;
    long long grid = (n_threads + block - 1) / block;

    qattn_cumprod_kernel<<<(unsigned)grid, block>>>(x, w, out, n_threads);
}

// round 2
// speedup vs baseline: 1.1390x; 1.1390x over previous
#include <cuda_runtime.h>

// QAttentionLayer: out[..., i] = cumprod_{j<=i}( cos(x_j) * cos(w_j) )
// x: [16384, 256, 10] fp32. Row = 10 floats; lcm(10,4)=20 -> 5-lane groups,
// each lane owns ONE contiguous float4 (perfect coalescing), cross-lane
// prefix product via 2 SHFL.IDX. Weight cosines pre-expanded by a prep
// kernel into cwp[20] (position-indexed) so the main kernel needs a single
// L1-resident LDG.128 for its 4 weight factors.

#define NQ 10

__device__ float4 d_cwp4[5];   // cwp[p] = cos(w[p % 10]), p = 0..19

__global__ void qattn_prep(const float* __restrict__ w)
{
    int t = threadIdx.x;
    if (t < 20) {
        int q = (t >= NQ) ? t - NQ : t;
        reinterpret_cast<float*>(d_cwp4)[t] = __cosf(w[q]);
    }
}

__global__ __launch_bounds__(256)
void qattn_main(const float4* __restrict__ x4,
                float4* __restrict__ o4,
                int n_groups)
{
    int tid  = blockIdx.x * blockDim.x + threadIdx.x;
    int warp = tid >> 5;
    int lane = tid & 31;
    int gw   = lane / 5;          // group within warp: 0..6 (6 => idle lane 30/31)
    int k    = lane - gw * 5;     // float4 slot within group: 0..4
    int base = lane - k;          // first lane of this 5-lane group
    int group = warp * 6 + gw;
    bool active = (gw < 6) && (group < n_groups);

    long long idx = (long long)group * 5 + k;   // float4 index
    float4 a = active ? x4[idx] : make_float4(0.f, 0.f, 0.f, 0.f);

    // 4 weight cosines for positions p = 4k .. 4k+3 (single vector load, L1-hit)
    float4 cw = __ldg(&d_cwp4[k]);

    float c0 = __cosf(a.x) * cw.x;
    float c1 = __cosf(a.y) * cw.y;
    float c2 = __cosf(a.z) * cw.z;
    float c3 = __cosf(a.w) * cw.w;

    // Local segmented inclusive scan. The only in-thread row boundary in a
    // 20-float group (rows of 10) is at p=10 -> lane k=2, element j=2.
    bool r2 = (k == 2);
    float lp0 = c0;
    float lp1 = lp0 * c1;
    float lp2 = r2 ? c2 : lp1 * c2;
    float lp3 = lp2 * c3;

    // pub: lane's "scan contribution" = product since last row start within it.
    float pub = lp3;

    // Cross-lane exclusive prefix (2 IDX shuffles):
    //  lane1 needs T0;   lane2 needs T0*T1;  lane3 needs t2;  lane4 needs t2*T3
    float sA = __shfl_sync(0xffffffffu, pub, base + ((k >= 3) ? 2 : 0));
    float sB = __shfl_sync(0xffffffffu, pub, base + ((k == 4) ? 3 : 1));
    float pre = (k == 0) ? 1.0f
              : (k == 1 || k == 3) ? sA
              : sA * sB;

    float pre_hi = r2 ? 1.0f : pre;   // elements after the in-thread reset

    float4 r;
    r.x = lp0 * pre;
    r.y = lp1 * pre;
    r.z = lp2 * pre_hi;
    r.w = lp3 * pre_hi;

    if (active) o4[idx] = r;
}

extern "C" void kernel_launch(void* const* d_in, const int* in_sizes, int n_in,
                              void* d_out, int out_size)
{
    const float* x = (const float*)d_in[0];   // [16384*256*10] fp32
    const float* w = (const float*)d_in[1];   // [10] fp32
    float* out = (float*)d_out;

    long long total   = (long long)in_sizes[0];   // 41,943,040 floats
    int n_groups      = (int)(total / 20);        // 2,097,152 groups of 20 floats
    long long warps   = ((long long)n_groups + 5) / 6;
    long long threads = warps * 32;
    int block = 256;
    long long grid = (threads + block - 1) / block;

    qattn_prep<<<1, 32>>>(w);
    qattn_main<<<(unsigned)grid, block>>>(reinterpret_cast<const float4*>(x),
                                          reinterpret_cast<float4*>(out),
                                          n_groups);
}

// round 3
// speedup vs baseline: 1.2539x; 1.1009x over previous
#include <cuda_runtime.h>

// QAttentionLayer: out[..., i] = cumprod_{j<=i}( cos(x_j) * cos(w_j) )
// x: [16384, 256, 10] fp32. Rows of 10 floats; lcm(10,4)=20 -> 5-lane groups,
// each lane owns ONE contiguous float4 (perfect coalescing), cross-lane prefix
// product via 2 SHFL.IDX. ILP=4: each thread processes 4 independent tiles
// with all loads front-batched (MLP_p1=4) to cover DRAM latency.

#define NQ 10
#define ILP 4

__device__ float4 d_cwp4[5];   // cwp[p] = cos(w[p % 10]), p = 0..19

__global__ void qattn_prep(const float* __restrict__ w)
{
    int t = threadIdx.x;
    if (t < 20) {
        int q = (t >= NQ) ? t - NQ : t;
        reinterpret_cast<float*>(d_cwp4)[t] = __cosf(w[q]);
    }
}

__global__ __launch_bounds__(256)
void qattn_main(const float4* __restrict__ x4,
                float4* __restrict__ o4,
                int n_groups)
{
    int tid  = blockIdx.x * blockDim.x + threadIdx.x;
    int warp = tid >> 5;
    int lane = tid & 31;
    int gw   = lane / 5;          // group slot within warp tile: 0..6 (6 => idle)
    int k    = lane - gw * 5;     // float4 slot within group: 0..4
    int base = lane - k;          // first lane of this 5-lane group
    bool lane_ok = (gw < 6);

    // Precompute per-lane constants once (amortized over ILP tiles)
    float4 cw = __ldg(&d_cwp4[k]);
    bool r2 = (k == 2);                         // in-thread row boundary lane
    int srcA = base + ((k >= 3) ? 2 : 0);
    int srcB = base + ((k == 4) ? 3 : 1);

    long long g0 = (long long)warp * (6 * ILP) + gw;   // group of tile 0

    bool act[ILP];
    long long idx[ILP];
    float4 a[ILP];
    // Front-batch ALL loads: MLP = ILP
#pragma unroll
    for (int it = 0; it < ILP; it++) {
        long long g = g0 + it * 6;
        act[it] = lane_ok && (g < n_groups);
        idx[it] = g * 5 + k;
        a[it] = act[it] ? x4[idx[it]] : make_float4(0.f, 0.f, 0.f, 0.f);
    }

    float4 r[ILP];
#pragma unroll
    for (int it = 0; it < ILP; it++) {
        float c0 = __cosf(a[it].x) * cw.x;
        float c1 = __cosf(a[it].y) * cw.y;
        float c2 = __cosf(a[it].z) * cw.z;
        float c3 = __cosf(a[it].w) * cw.w;

        // Local segmented inclusive scan (reset at p=10 -> k==2, j==2)
        float lp0 = c0;
        float lp1 = lp0 * c1;
        float lp2 = r2 ? c2 : lp1 * c2;
        float lp3 = lp2 * c3;

        // Cross-lane exclusive prefix (2 IDX shuffles)
        float sA = __shfl_sync(0xffffffffu, lp3, srcA);
        float sB = __shfl_sync(0xffffffffu, lp3, srcB);
        float pre = (k == 0) ? 1.0f
                  : (k == 1 || k == 3) ? sA
                  : sA * sB;
        float pre_hi = r2 ? 1.0f : pre;

        r[it].x = lp0 * pre;
        r[it].y = lp1 * pre;
        r[it].z = lp2 * pre_hi;
        r[it].w = lp3 * pre_hi;
    }

#pragma unroll
    for (int it = 0; it < ILP; it++)
        if (act[it]) o4[idx[it]] = r[it];
}

extern "C" void kernel_launch(void* const* d_in, const int* in_sizes, int n_in,
                              void* d_out, int out_size)
{
    const float* x = (const float*)d_in[0];   // [16384*256*10] fp32
    const float* w = (const float*)d_in[1];   // [10] fp32
    float* out = (float*)d_out;

    long long total = (long long)in_sizes[0];   // 41,943,040 floats
    int n_groups    = (int)(total / 20);        // 2,097,152 groups of 20 floats
    long long warps = ((long long)n_groups + 6 * ILP - 1) / (6 * ILP);
    long long threads = warps * 32;
    int block = 256;
    long long grid = (threads + block - 1) / block;

    qattn_prep<<<1, 32>>>(w);
    qattn_main<<<(unsigned)grid, block>>>(reinterpret_cast<const float4*>(x),
                                          reinterpret_cast<float4*>(out),
                                          n_groups);
}

// round 4
// speedup vs baseline: 1.3024x; 1.0387x over previous
#include <cuda_runtime.h>

// QAttentionLayer: out[..., i] = cumprod_{j<=i}( cos(x_j) * cos(w_j) )
// x: [16384, 256, 10] fp32. Rows of 10 floats; lcm(10,4)=20 -> 5-lane groups,
// each lane owns ONE contiguous float4 (perfect coalescing), cross-lane prefix
// product via 2 SHFL.IDX. ILP=8: 8 front-batched LDG.128 per thread (MLP_p1=8)
// to saturate HBM. Single kernel (weight cosines computed inline). 32-bit
// indices. __ldcs/__stcs streaming hints (335MB stream >> 126MB L2).

#define NQ 10
#define ILP 8

__global__ __launch_bounds__(256)
void qattn_main(const float4* __restrict__ x4,
                float4* __restrict__ o4,
                const float* __restrict__ w,
                int n_groups)
{
    int tid  = blockIdx.x * blockDim.x + threadIdx.x;
    int warp = tid >> 5;
    int lane = tid & 31;
    int gw   = lane / 5;          // group slot within warp tile: 0..6 (6 => idle)
    int k    = lane - gw * 5;     // float4 slot within group: 0..4
    int base = lane - k;          // first lane of this 5-lane group
    bool lane_ok = (gw < 6);

    // Weight cosines for positions p = 4k..4k+3 (q = p mod 10), computed once.
    float cw0, cw1, cw2, cw3;
    {
        int p = 4 * k;
        int q0 = (p     < NQ) ? p     : p - NQ;
        int q1 = (p + 1 < NQ) ? p + 1 : p + 1 - NQ;
        int q2 = (p + 2 < NQ) ? p + 2 : p + 2 - NQ;
        int q3 = (p + 3 < NQ) ? p + 3 : p + 3 - NQ;
        cw0 = __cosf(__ldg(&w[q0]));
        cw1 = __cosf(__ldg(&w[q1]));
        cw2 = __cosf(__ldg(&w[q2]));
        cw3 = __cosf(__ldg(&w[q3]));
    }

    bool r2 = (k == 2);                          // in-thread row boundary lane
    int srcA = base + ((k >= 3) ? 2 : 0);
    int srcB = base + ((k == 4) ? 3 : 1);

    int g0 = warp * (6 * ILP) + gw;              // group handled in tile 0

    bool act[ILP];
    int idx[ILP];
    float4 a[ILP];
    // Front-batch ALL loads: MLP = ILP
#pragma unroll
    for (int it = 0; it < ILP; it++) {
        int g = g0 + it * 6;
        act[it] = lane_ok && (g < n_groups);
        idx[it] = g * 5 + k;                     // < 10.5M, fits int32
        a[it] = act[it] ? __ldcs(&x4[idx[it]]) : make_float4(0.f, 0.f, 0.f, 0.f);
    }

#pragma unroll
    for (int it = 0; it < ILP; it++) {
        float c0 = __cosf(a[it].x) * cw0;
        float c1 = __cosf(a[it].y) * cw1;
        float c2 = __cosf(a[it].z) * cw2;
        float c3 = __cosf(a[it].w) * cw3;

        // Local segmented inclusive scan (reset at p=10 -> k==2, j==2)
        float lp0 = c0;
        float lp1 = lp0 * c1;
        float lp2 = r2 ? c2 : lp1 * c2;
        float lp3 = lp2 * c3;

        // Cross-lane exclusive prefix (2 IDX shuffles)
        float sA = __shfl_sync(0xffffffffu, lp3, srcA);
        float sB = __shfl_sync(0xffffffffu, lp3, srcB);
        float pre = (k == 0) ? 1.0f
                  : (k == 1 || k == 3) ? sA
                  : sA * sB;
        float pre_hi = r2 ? 1.0f : pre;

        float4 r;
        r.x = lp0 * pre;
        r.y = lp1 * pre;
        r.z = lp2 * pre_hi;
        r.w = lp3 * pre_hi;

        if (act[it]) __stcs(&o4[idx[it]], r);
    }
}

extern "C" void kernel_launch(void* const* d_in, const int* in_sizes, int n_in,
                              void* d_out, int out_size)
{
    const float* x = (const float*)d_in[0];   // [16384*256*10] fp32
    const float* w = (const float*)d_in[1];   // [10] fp32
    float* out = (float*)d_out;

    long long total = (long long)in_sizes[0];   // 41,943,040 floats
    int n_groups    = (int)(total / 20);        // 2,097,152 groups of 20 floats
    long long warps = ((long long)n_groups + 6 * ILP - 1) / (6 * ILP);
    long long threads = warps * 32;
    int block = 256;
    long long grid = (threads + block - 1) / block;

    qattn_main<<<(unsigned)grid, block>>>(reinterpret_cast<const float4*>(x),
                                          reinterpret_cast<float4*>(out),
                                          w, n_groups);
}